// round 16
// baseline (speedup 1.0000x reference)
#include <cuda_runtime.h>
#include <cuda_fp16.h>
#include <math.h>

#define N_NODES 50000
#define N_EDGES 800000
#define ET (N_EDGES + N_NODES)   // edges + self loops = 850000
#define F_IN 128
#define H 256
#define G_GRAPHS 500
#define FC1 196
#define D_OUT 10
#define NEG 0.2f
#define NB_SCAN ((N_NODES + 1023) / 1024)   // 49 scan blocks

// ---------------- scratch (static device globals; no allocation) ----------------
__device__ __align__(16) __half g_featH[(size_t)N_NODES * H];   // h = A@W (fp16, GEMM out)
__device__ __align__(16) __half g_featBH[(size_t)N_NODES * H];  // attention out (fp16, next A)
__device__ __align__(16) __half g_x16[(size_t)N_NODES * F_IN];  // fp16 copy of x
__device__ __align__(16) __half g_W16[3][H * H];                // fp16 weights (W1 uses 128 rows)
__device__ float g_dsp[2][N_NODES];              // per-colblock dot partials (s)
__device__ float g_ddp[2][N_NODES];              // per-colblock dot partials (d)
__device__ float g_e[ET];                        // per-edge exp(e - m) (slow path)
__device__ int   g_deg[N_NODES];
__device__ int   g_off[N_NODES + 1];             // CSR row offsets (by dst)
__device__ int   g_pos[N_NODES];
__device__ int   g_srcs[ET];                     // CSR column indices (src node)
__device__ int   g_bsum[NB_SCAN];
__device__ int   g_bpre[NB_SCAN];
__device__ float g_hg[G_GRAPHS * H];             // pooled per-graph sums
__device__ float g_cnt[G_GRAPHS];
__device__ float g_fc1[G_GRAPHS * FC1];

// ================= CSR build =================
__global__ void zero_deg() {
    int i = blockIdx.x * blockDim.x + threadIdx.x;
    if (i < N_NODES) g_deg[i] = 0;
    if (i < G_GRAPHS * H) g_hg[i] = 0.f;
    if (i < G_GRAPHS) g_cnt[i] = 0.f;
}

__global__ void count_all(const int* __restrict__ ei, const int* __restrict__ batch) {
    int e = blockIdx.x * blockDim.x + threadIdx.x;
    if (e < ET) {
        int d = (e < N_EDGES) ? ei[N_EDGES + e] : (e - N_EDGES);
        atomicAdd(&g_deg[d], 1);
    }
    if (e < N_NODES) atomicAdd(&g_cnt[batch[e]], 1.f);
}

__global__ __launch_bounds__(1024) void scan_local() {
    __shared__ int ws[32];
    int tid = threadIdx.x, lane = tid & 31, wid = tid >> 5;
    int i = blockIdx.x * 1024 + tid;
    int v = (i < N_NODES) ? g_deg[i] : 0;
    int incl = v;
#pragma unroll
    for (int o = 1; o < 32; o <<= 1) {
        int t = __shfl_up_sync(0xFFFFFFFFu, incl, o);
        if (lane >= o) incl += t;
    }
    if (lane == 31) ws[wid] = incl;
    __syncthreads();
    if (wid == 0) {
        int w = ws[lane];
#pragma unroll
        for (int o = 1; o < 32; o <<= 1) {
            int t = __shfl_up_sync(0xFFFFFFFFu, w, o);
            if (lane >= o) w += t;
        }
        ws[lane] = w;
    }
    __syncthreads();
    int excl = (wid ? ws[wid - 1] : 0) + incl - v;
    if (i < N_NODES) g_off[i] = excl;
    if (tid == 0) g_bsum[blockIdx.x] = ws[31];
}

__global__ void scan_bsums() {
    __shared__ int sh[64];
    int tid = threadIdx.x;
    int v = (tid < NB_SCAN) ? g_bsum[tid] : 0;
    sh[tid] = v;
    __syncthreads();
#pragma unroll
    for (int o = 1; o < 64; o <<= 1) {
        int t = (tid >= o) ? sh[tid - o] : 0;
        __syncthreads();
        sh[tid] += t;
        __syncthreads();
    }
    if (tid < NB_SCAN) g_bpre[tid] = sh[tid] - v;
}

__global__ void scan_add() {
    int i = blockIdx.x * blockDim.x + threadIdx.x;
    if (i == 0) g_off[N_NODES] = ET;
    if (i < N_NODES) {
        int o = g_off[i] + g_bpre[i >> 10];
        g_off[i] = o;
        g_pos[i] = o;
    }
}

__global__ void scatter_edges(const int* __restrict__ ei) {
    int e = blockIdx.x * blockDim.x + threadIdx.x;
    if (e >= ET) return;
    int s, d;
    if (e < N_EDGES) { s = ei[e]; d = ei[N_EDGES + e]; }
    else             { s = d = e - N_EDGES; }
    int idx = atomicAdd(&g_pos[d], 1);
    g_srcs[idx] = s;
}

// ================= fp32 -> fp16 conversion of x and all weights =================
#define X_ELEMS (N_NODES * F_IN)          // 6,400,000
#define W1_ELEMS (F_IN * H)               // 32,768
#define W23_ELEMS (H * H)                 // 65,536
#define CONV_TOT (X_ELEMS + W1_ELEMS + 2 * W23_ELEMS)

__global__ void conv_all(const float* __restrict__ x, const float* __restrict__ W1,
                         const float* __restrict__ W2, const float* __restrict__ W3) {
    int i4 = blockIdx.x * blockDim.x + threadIdx.x;   // float4 index
    size_t off = (size_t)i4 * 4;
    if (off >= CONV_TOT) return;
    const float* src;
    __half* dst;
    if (off < X_ELEMS)                       { src = x + off;  dst = g_x16 + off; }
    else if (off < X_ELEMS + W1_ELEMS)       { size_t o = off - X_ELEMS;              src = W1 + o; dst = g_W16[0] + o; }
    else if (off < X_ELEMS + W1_ELEMS + W23_ELEMS) { size_t o = off - X_ELEMS - W1_ELEMS; src = W2 + o; dst = g_W16[1] + o; }
    else                                     { size_t o = off - X_ELEMS - W1_ELEMS - W23_ELEMS; src = W3 + o; dst = g_W16[2] + o; }
    float4 v = *(const float4*)src;
    __half2* d2 = (__half2*)dst;
    d2[0] = __floats2half2_rn(v.x, v.y);
    d2[1] = __floats2half2_rn(v.z, v.w);
}

// ================= fp16 TC GEMM (3-stage cp.async, m16n8k16, ldmatrix) =================
// Grid-per-tile (R13 known-good form). Dynamic SMEM.
#define AS_STRIDE 40    // halves per A row (32 + 8 pad)
#define BS_STRIDE 136   // halves per B k-row (128 + 8 pad)
#define AS_HALVES (128 * AS_STRIDE)                 // 5120 halves / stage
#define BS_HALVES (32 * BS_STRIDE)                  // 4352 halves / stage
#define STAGE_HALVES (AS_HALVES + BS_HALVES)        // 9472
#define GEMM_SMEM_BYTES (3 * STAGE_HALVES * 2 + 2 * 128 * 4)   // 57856

__device__ __forceinline__ void cp16(unsigned dst, const void* src) {
    asm volatile("cp.async.cg.shared.global [%0], [%1], 16;" :: "r"(dst), "l"(src));
}

__global__ __launch_bounds__(256) void sgemm_tc(const __half* __restrict__ A,
                                                const __half* __restrict__ Wl,
                                                const float* __restrict__ avs,
                                                const float* __restrict__ avd,
                                                int M, int K) {
    extern __shared__ __half smem[];
    __half* As3 = smem;
    __half* Bs3 = smem + 3 * AS_HALVES;
    float* sds = (float*)(smem + 3 * STAGE_HALVES);
    float* sdd = sds + 128;

    int tid = threadIdx.x;
    int wid = tid >> 5, lane = tid & 31;
    int grp = lane >> 2, t4 = lane & 3;
    int wm = wid >> 2, wn = wid & 3;           // warp grid 2x4, warp tile 64x32
    int row0 = blockIdx.y * 128;
    int col0 = blockIdx.x * 128;

    int ac0 = tid * 2;
    int bc0 = tid * 2;

    float acc[4][4][4] = {};
    int nit = K >> 5;

    if (tid < 128) { sds[tid] = 0.f; sdd[tid] = 0.f; }

    auto issue = [&](int it) {
        int k0 = it * 32;
        int buf = it % 3;
        unsigned a_base = (unsigned)__cvta_generic_to_shared(As3 + buf * AS_HALVES);
        unsigned b_base = (unsigned)__cvta_generic_to_shared(Bs3 + buf * BS_HALVES);
#pragma unroll
        for (int q = 0; q < 2; q++) {
            int c = ac0 + q;
            int row = c >> 2, koff = (c & 3) * 8;
            if (row0 + row < M)
                cp16(a_base + (row * AS_STRIDE + koff) * 2,
                     A + (size_t)(row0 + row) * K + k0 + koff);
            int cb = bc0 + q;
            int krow = cb >> 4, noff = (cb & 15) * 8;
            cp16(b_base + (krow * BS_STRIDE + noff) * 2,
                 Wl + (size_t)(k0 + krow) * 256 + col0 + noff);
        }
        asm volatile("cp.async.commit_group;");
    };

    auto comp = [&](int b) {
        unsigned a_base = (unsigned)__cvta_generic_to_shared(As3 + b * AS_HALVES);
        unsigned b_base = (unsigned)__cvta_generic_to_shared(Bs3 + b * BS_HALVES);
        int lr = lane & 15, lh = (lane >> 4) << 3;
#pragma unroll
        for (int ks = 0; ks < 32; ks += 16) {
            unsigned bf[2][4];
#pragma unroll
            for (int jj = 0; jj < 2; jj++) {
                unsigned addr = b_base + ((ks + lr) * BS_STRIDE + wn * 32 + jj * 16 + lh) * 2;
                asm volatile("ldmatrix.sync.aligned.m8n8.x4.trans.shared.b16 {%0,%1,%2,%3}, [%4];"
                             : "=r"(bf[jj][0]), "=r"(bf[jj][1]), "=r"(bf[jj][2]), "=r"(bf[jj][3])
                             : "r"(addr));
            }
#pragma unroll
            for (int i = 0; i < 4; i++) {
                unsigned af0, af1, af2, af3;
                unsigned addr = a_base + ((wm * 64 + i * 16 + lr) * AS_STRIDE + ks + lh) * 2;
                asm volatile("ldmatrix.sync.aligned.m8n8.x4.shared.b16 {%0,%1,%2,%3}, [%4];"
                             : "=r"(af0), "=r"(af1), "=r"(af2), "=r"(af3)
                             : "r"(addr));
#pragma unroll
                for (int jj = 0; jj < 2; jj++) {
#pragma unroll
                    for (int ns = 0; ns < 2; ns++) {
                        float* c = acc[i][jj * 2 + ns];
                        asm volatile("mma.sync.aligned.m16n8k16.row.col.f32.f16.f16.f32 "
                                     "{%0,%1,%2,%3}, {%4,%5,%6,%7}, {%8,%9}, {%0,%1,%2,%3};"
                                     : "+f"(c[0]), "+f"(c[1]), "+f"(c[2]), "+f"(c[3])
                                     : "r"(af0), "r"(af1), "r"(af2), "r"(af3),
                                       "r"(bf[jj][ns * 2]), "r"(bf[jj][ns * 2 + 1]));
                    }
                }
            }
        }
    };

    // ---- 3-stage pipelined mainloop: one __syncthreads per iteration ----
    issue(0);
    if (nit > 1) issue(1);
    for (int it = 0; it < nit; it++) {
        if (it + 1 < nit) asm volatile("cp.async.wait_group 1;");
        else              asm volatile("cp.async.wait_group 0;");
        __syncthreads();   // publishes stage it; retires all readers of comp(it-1)
        comp(it % 3);
        if (it + 2 < nit) issue(it + 2);   // buffer (it+2)%3 == (it-1)%3: readers passed sync
    }

    // ---- attention-dot epilogue (fp32-exact from acc; shfl-reduce over t4 lanes) ----
    float a_s_r[8], a_d_r[8];
#pragma unroll
    for (int j = 0; j < 4; j++) {
        int col = col0 + wn * 32 + j * 8 + t4 * 2;
        a_s_r[j * 2 + 0] = avs[col];     a_s_r[j * 2 + 1] = avs[col + 1];
        a_d_r[j * 2 + 0] = avd[col];     a_d_r[j * 2 + 1] = avd[col + 1];
    }
    __syncthreads();
#pragma unroll
    for (int i = 0; i < 4; i++) {
        float ps0 = 0.f, pd0 = 0.f, ps1 = 0.f, pd1 = 0.f;
#pragma unroll
        for (int j = 0; j < 4; j++) {
            ps0 += acc[i][j][0] * a_s_r[j * 2] + acc[i][j][1] * a_s_r[j * 2 + 1];
            pd0 += acc[i][j][0] * a_d_r[j * 2] + acc[i][j][1] * a_d_r[j * 2 + 1];
            ps1 += acc[i][j][2] * a_s_r[j * 2] + acc[i][j][3] * a_s_r[j * 2 + 1];
            pd1 += acc[i][j][2] * a_d_r[j * 2] + acc[i][j][3] * a_d_r[j * 2 + 1];
        }
        ps0 += __shfl_xor_sync(0xFFFFFFFFu, ps0, 1); ps0 += __shfl_xor_sync(0xFFFFFFFFu, ps0, 2);
        pd0 += __shfl_xor_sync(0xFFFFFFFFu, pd0, 1); pd0 += __shfl_xor_sync(0xFFFFFFFFu, pd0, 2);
        ps1 += __shfl_xor_sync(0xFFFFFFFFu, ps1, 1); ps1 += __shfl_xor_sync(0xFFFFFFFFu, ps1, 2);
        pd1 += __shfl_xor_sync(0xFFFFFFFFu, pd1, 1); pd1 += __shfl_xor_sync(0xFFFFFFFFu, pd1, 2);
        if (t4 == 0) {
            int rl = wm * 64 + i * 16 + grp;
            atomicAdd(&sds[rl], ps0);     atomicAdd(&sdd[rl], pd0);
            atomicAdd(&sds[rl + 8], ps1); atomicAdd(&sdd[rl + 8], pd1);
        }
    }
    __syncthreads();
    if (tid < 128) {
        int row = row0 + tid;
        if (row < M) {
            g_dsp[blockIdx.x][row] = sds[tid];
            g_ddp[blockIdx.x][row] = sdd[tid];
        }
    }

    // ---- fp16 featH store ----
#pragma unroll
    for (int i = 0; i < 4; i++) {
#pragma unroll
        for (int j = 0; j < 4; j++) {
            int row = row0 + wm * 64 + i * 16 + grp;
            int col = col0 + wn * 32 + j * 8 + t4 * 2;
            if (row < M)
                *(__half2*)(g_featH + (size_t)row * 256 + col) =
                    __floats2half2_rn(acc[i][j][0], acc[i][j][1]);
            if (row + 8 < M)
                *(__half2*)(g_featH + (size_t)(row + 8) * 256 + col) =
                    __floats2half2_rn(acc[i][j][2], acc[i][j][3]);
        }
    }
}

// ================= fused softmax + aggregate (warp per dst) =================
__device__ __forceinline__ float node_as(int i) { return g_dsp[0][i] + g_dsp[1][i]; }
__device__ __forceinline__ float node_ad(int i) { return g_ddp[0][i] + g_ddp[1][i]; }

__device__ __forceinline__ void agg_edge(int sj, float aj, int lane, float acc[8]) {
    const uint4* hs = (const uint4*)(g_featH + (size_t)sj * H);
    uint4 q = hs[lane];
    const __half2* h2 = (const __half2*)&q;
#pragma unroll
    for (int c = 0; c < 4; c++) {
        float2 f = __half22float2(h2[c]);
        acc[c * 2 + 0] += aj * f.x;
        acc[c * 2 + 1] += aj * f.y;
    }
}

// unrolled-by-4: four independent 512B gathers in flight per warp
__device__ __forceinline__ void agg_sweep(float a, int s, int cnt, int lane, float acc[8]) {
    int j = 0;
    for (; j + 4 <= cnt; j += 4) {
        float aj0 = __shfl_sync(0xFFFFFFFFu, a, j);
        int   sj0 = __shfl_sync(0xFFFFFFFFu, s, j);
        float aj1 = __shfl_sync(0xFFFFFFFFu, a, j + 1);
        int   sj1 = __shfl_sync(0xFFFFFFFFu, s, j + 1);
        float aj2 = __shfl_sync(0xFFFFFFFFu, a, j + 2);
        int   sj2 = __shfl_sync(0xFFFFFFFFu, s, j + 2);
        float aj3 = __shfl_sync(0xFFFFFFFFu, a, j + 3);
        int   sj3 = __shfl_sync(0xFFFFFFFFu, s, j + 3);
        uint4 q0 = ((const uint4*)(g_featH + (size_t)sj0 * H))[lane];
        uint4 q1 = ((const uint4*)(g_featH + (size_t)sj1 * H))[lane];
        uint4 q2 = ((const uint4*)(g_featH + (size_t)sj2 * H))[lane];
        uint4 q3 = ((const uint4*)(g_featH + (size_t)sj3 * H))[lane];
        const __half2* h0 = (const __half2*)&q0;
        const __half2* h1 = (const __half2*)&q1;
        const __half2* h2 = (const __half2*)&q2;
        const __half2* h3 = (const __half2*)&q3;
#pragma unroll
        for (int c = 0; c < 4; c++) {
            float2 f0 = __half22float2(h0[c]);
            float2 f1 = __half22float2(h1[c]);
            float2 f2 = __half22float2(h2[c]);
            float2 f3 = __half22float2(h3[c]);
            acc[c * 2 + 0] += aj0 * f0.x + aj1 * f1.x + aj2 * f2.x + aj3 * f3.x;
            acc[c * 2 + 1] += aj0 * f0.y + aj1 * f1.y + aj2 * f2.y + aj3 * f3.y;
        }
    }
    for (; j < cnt; j++) {
        float aj = __shfl_sync(0xFFFFFFFFu, a, j);
        int   sj = __shfl_sync(0xFFFFFFFFu, s, j);
        agg_edge(sj, aj, lane, acc);
    }
}

__device__ __forceinline__ void gat_attn_body(int warp, int lane, float acc[8]) {
    int beg = g_off[warp], end = g_off[warp + 1];
    int deg = end - beg;
    float ad = node_ad(warp);

    if (deg <= 32) {
        bool valid = lane < deg;
        int s = valid ? g_srcs[beg + lane] : 0;
        float e = -3.4e38f;
        if (valid) {
            e = node_as(s) + ad;
            e = (e > 0.f) ? e : NEG * e;
        }
        float m = e;
#pragma unroll
        for (int o = 16; o; o >>= 1) m = fmaxf(m, __shfl_xor_sync(0xFFFFFFFFu, m, o));
        float ex = valid ? expf(e - m) : 0.f;
        float denom = ex;
#pragma unroll
        for (int o = 16; o; o >>= 1) denom += __shfl_xor_sync(0xFFFFFFFFu, denom, o);
        float a = ex / fmaxf(denom, 1e-16f);
        agg_sweep(a, s, deg, lane, acc);
    } else {
        float m = -3.4e38f;
        for (int i = beg + lane; i < end; i += 32) {
            float e = node_as(g_srcs[i]) + ad;
            e = (e > 0.f) ? e : NEG * e;
            m = fmaxf(m, e);
        }
#pragma unroll
        for (int o = 16; o; o >>= 1) m = fmaxf(m, __shfl_xor_sync(0xFFFFFFFFu, m, o));
        float denom = 0.f;
        for (int i = beg + lane; i < end; i += 32) {
            float e = node_as(g_srcs[i]) + ad;
            e = (e > 0.f) ? e : NEG * e;
            float ex = expf(e - m);
            g_e[i] = ex;
            denom += ex;
        }
#pragma unroll
        for (int o = 16; o; o >>= 1) denom += __shfl_xor_sync(0xFFFFFFFFu, denom, o);
        float inv = 1.f / fmaxf(denom, 1e-16f);
        for (int i0 = beg; i0 < end; i0 += 32) {
            int i = i0 + lane;
            float a = 0.f; int s = 0;
            if (i < end) { s = g_srcs[i]; a = g_e[i] * inv; }
            agg_sweep(a, s, min(32, end - i0), lane, acc);
        }
    }
}

// layers 1-2: write fp16 featBH (next GEMM A)
__global__ void gat_attn(const float* __restrict__ bias) {
    int warp = (blockIdx.x * blockDim.x + threadIdx.x) >> 5;
    int lane = threadIdx.x & 31;
    if (warp >= N_NODES) return;
    float acc[8] = {};
    gat_attn_body(warp, lane, acc);
    const float* bp = bias + lane * 8;
    uint4 o;
    __half2 h0 = __floats2half2_rn(fmaxf(acc[0] + bp[0], 0.f), fmaxf(acc[1] + bp[1], 0.f));
    __half2 h1 = __floats2half2_rn(fmaxf(acc[2] + bp[2], 0.f), fmaxf(acc[3] + bp[3], 0.f));
    __half2 h2 = __floats2half2_rn(fmaxf(acc[4] + bp[4], 0.f), fmaxf(acc[5] + bp[5], 0.f));
    __half2 h3 = __floats2half2_rn(fmaxf(acc[6] + bp[6], 0.f), fmaxf(acc[7] + bp[7], 0.f));
    o.x = *(unsigned*)&h0; o.y = *(unsigned*)&h1;
    o.z = *(unsigned*)&h2; o.w = *(unsigned*)&h3;
    *(uint4*)(g_featBH + (size_t)warp * H + lane * 8) = o;
}

// layer 3: pool directly into g_hg
__global__ void gat_attn_pool(const float* __restrict__ bias, const int* __restrict__ batch) {
    int warp = (blockIdx.x * blockDim.x + threadIdx.x) >> 5;
    int lane = threadIdx.x & 31;
    if (warp >= N_NODES) return;
    float acc[8] = {};
    gat_attn_body(warp, lane, acc);
    int g = batch[warp];
    float* hg = g_hg + (size_t)g * H + lane * 8;
    const float* bp = bias + lane * 8;
#pragma unroll
    for (int c = 0; c < 8; c++)
        atomicAdd(&hg[c], fmaxf(acc[c] + bp[c], 0.f));
}

// ================= MLP head =================
__global__ void fc1_kernel(const float* __restrict__ w, const float* __restrict__ b) {
    __shared__ float sh[H];
    int g = blockIdx.x;
    float c = fmaxf(g_cnt[g], 1.f);
    sh[threadIdx.x] = g_hg[(size_t)g * H + threadIdx.x] / c;
    __syncthreads();
    int j = threadIdx.x;
    if (j < FC1) {
        float acc = b[j];
#pragma unroll 8
        for (int k = 0; k < H; k++)
            acc += sh[k] * w[(size_t)k * FC1 + j];
        g_fc1[(size_t)g * FC1 + j] = fmaxf(acc, 0.f);
    }
}

__global__ void fc2_kernel(const float* __restrict__ w, const float* __restrict__ b,
                           float* __restrict__ out) {
    int g = blockIdx.x;
    int o = threadIdx.x;
    if (o >= D_OUT) return;
    float acc = b[o];
#pragma unroll 4
    for (int k = 0; k < FC1; k++)
        acc += g_fc1[(size_t)g * FC1 + k] * w[(size_t)k * D_OUT + o];
    out[(size_t)g * D_OUT + o] = acc;
}

// ================= host =================
extern "C" void kernel_launch(void* const* d_in, const int* in_sizes, int n_in,
                              void* d_out, int out_size) {
    const float* x     = (const float*)d_in[0];
    const int*   ei    = (const int*)d_in[1];
    const int*   batch = (const int*)d_in[2];
    const float* W1 = (const float*)d_in[3];
    const float* a1s = (const float*)d_in[4];
    const float* a1d = (const float*)d_in[5];
    const float* b1 = (const float*)d_in[6];
    const float* W2 = (const float*)d_in[7];
    const float* a2s = (const float*)d_in[8];
    const float* a2d = (const float*)d_in[9];
    const float* b2 = (const float*)d_in[10];
    const float* W3 = (const float*)d_in[11];
    const float* a3s = (const float*)d_in[12];
    const float* a3d = (const float*)d_in[13];
    const float* b3 = (const float*)d_in[14];
    const float* fc1_w = (const float*)d_in[15];
    const float* fc1_b = (const float*)d_in[16];
    const float* fc2_w = (const float*)d_in[17];
    const float* fc2_b = (const float*)d_in[18];

    __half* x16 = nullptr;
    __half* featBH = nullptr;
    __half* W16 = nullptr;
    cudaGetSymbolAddress((void**)&x16, g_x16);
    cudaGetSymbolAddress((void**)&featBH, g_featBH);
    cudaGetSymbolAddress((void**)&W16, g_W16);

    static cudaStream_t s2 = nullptr;
    static cudaEvent_t evA = nullptr, evB = nullptr;
    if (!s2) {
        cudaStreamCreateWithFlags(&s2, cudaStreamNonBlocking);
        cudaEventCreateWithFlags(&evA, cudaEventDisableTiming);
        cudaEventCreateWithFlags(&evB, cudaEventDisableTiming);
        cudaFuncSetAttribute(sgemm_tc, cudaFuncAttributeMaxDynamicSharedMemorySize,
                             GEMM_SMEM_BYTES);
    }

    dim3 gemmGrid(2, (N_NODES + 127) / 128);
    int edgeBlocks = (ET + 255) / 256;
    int nodeBlocksW = ((size_t)N_NODES * 32 + 255) / 256;
    int nodeBlocks = (N_NODES + 255) / 256;

    // ---- main: zero + counts, then conversions + layer-1 GEMM ----
    zero_deg<<<(G_GRAPHS * H + 255) / 256, 256>>>();                           // #1
    count_all<<<edgeBlocks, 256>>>(ei, batch);                                 // #2
    cudaEventRecord(evA, 0);

    conv_all<<<(CONV_TOT / 4 + 255) / 256, 256>>>(x, W1, W2, W3);              // #3
    sgemm_tc<<<gemmGrid, 256, GEMM_SMEM_BYTES>>>(x16, W16, a1s, a1d, N_NODES, F_IN);  // #4

    // ---- side: CSR build, concurrent with conv + GEMM1 ----
    cudaStreamWaitEvent(s2, evA, 0);
    scan_local<<<NB_SCAN, 1024, 0, s2>>>();
    scan_bsums<<<1, 64, 0, s2>>>();
    scan_add<<<nodeBlocks, 256, 0, s2>>>();
    scatter_edges<<<edgeBlocks, 256, 0, s2>>>(ei);
    cudaEventRecord(evB, s2);
    cudaStreamWaitEvent(0, evB, 0);   // join before attention

    // ---- layer 1 attention ----
    gat_attn<<<nodeBlocksW, 256>>>(b1);

    // ---- layer 2 ----
    sgemm_tc<<<gemmGrid, 256, GEMM_SMEM_BYTES>>>(featBH, W16 + H * H, a2s, a2d, N_NODES, H);
    gat_attn<<<nodeBlocksW, 256>>>(b2);

    // ---- layer 3 (pool fused) ----
    sgemm_tc<<<gemmGrid, 256, GEMM_SMEM_BYTES>>>(featBH, W16 + 2 * H * H, a3s, a3d, N_NODES, H);
    gat_attn_pool<<<nodeBlocksW, 256>>>(b3, batch);

    // ---- MLP head ----
    fc1_kernel<<<G_GRAPHS, H>>>(fc1_w, fc1_b);
    fc2_kernel<<<G_GRAPHS, 32>>>(fc2_w, fc2_b, (float*)d_out);
}